// round 11
// baseline (speedup 1.0000x reference)
#include <cuda_runtime.h>
#include <math.h>
#include <stdint.h>

// ChordalPCWeightTransform — R10: TMA 1D bulk staging + 2x tile.
// Math identity (R4): the two per-label rolls cancel on the data and rotate
// only the weight vector:
//   out[b,l,p] = softmax_p( x[b,l,p] * w[(p - root) mod 12] ), p<12; w[12] at p=12
//   root = (row / 12) % 12
//
// Staging both directions via cp.async.bulk (1D, no tensor map): one 26 KB
// contiguous bulk read and one 26 KB bulk write per CTA, single-thread issue,
// maximal DRAM burst length, zero per-thread LSU staging traffic.

#define P 13
#define RPB 256
#define ROWS_PER_TILE 512
#define TILE_FLOATS (ROWS_PER_TILE * P)     // 6656 floats = 26624 B (mult of 16)
#define TILE_BYTES (TILE_FLOATS * 4)

__global__ __launch_bounds__(RPB)
void chordal_softmax_kernel(const float* __restrict__ x,
                            const float* __restrict__ w,
                            float* __restrict__ out)
{
    __shared__ alignas(128) float tile[TILE_FLOATS];
    __shared__ float ws[P];
    __shared__ alignas(8) uint64_t mbar;

    const int tid = threadIdx.x;
    if (tid < P) ws[tid] = __ldg(&w[tid]);

    const uint32_t mbar_a = (uint32_t)__cvta_generic_to_shared(&mbar);
    const uint32_t tile_a = (uint32_t)__cvta_generic_to_shared(tile);
    const long long base = (long long)blockIdx.x * TILE_FLOATS;

    if (tid == 0) {
        asm volatile("mbarrier.init.shared.b64 [%0], 1;" :: "r"(mbar_a) : "memory");
    }
    __syncthreads();

    // ---- single bulk load: global -> smem (26624 B, one TMA op) ----
    if (tid == 0) {
        asm volatile("mbarrier.arrive.expect_tx.shared.b64 _, [%0], %1;"
                     :: "r"(mbar_a), "r"((uint32_t)TILE_BYTES) : "memory");
        asm volatile("cp.async.bulk.shared::cta.global.mbarrier::complete_tx::bytes "
                     "[%0], [%1], %2, [%3];"
                     :: "r"(tile_a), "l"(x + base), "r"((uint32_t)TILE_BYTES),
                        "r"(mbar_a) : "memory");
    }
    // all threads wait for completion (phase 0)
    {
        uint32_t done;
        asm volatile(
            "{\n\t"
            ".reg .pred p;\n\t"
            "mbarrier.try_wait.parity.acquire.cta.shared::cta.b64 p, [%1], 0;\n\t"
            "selp.b32 %0, 1, 0, p;\n\t"
            "}" : "=r"(done) : "r"(mbar_a) : "memory");
        if (!done) {
            asm volatile(
                "{\n\t"
                ".reg .pred P1;\n\t"
                "WL_%=:\n\t"
                "mbarrier.try_wait.parity.acquire.cta.shared::cta.b64 P1, [%0], 0, 0x989680;\n\t"
                "@P1 bra.uni WD_%=;\n\t"
                "bra.uni WL_%=;\n\t"
                "WD_%=:\n\t"
                "}" :: "r"(mbar_a) : "memory");
        }
    }
    __syncthreads();

    // ---- per-thread weighted softmax, 2 rows per thread, in place ----
#pragma unroll
    for (int rr = 0; rr < 2; rr++) {
        const int lr   = tid + rr * RPB;                 // local row 0..511
        const int row  = blockIdx.x * ROWS_PER_TILE + lr;
        const int root = (row / 12) % 12;

        float v[P];
        float m = -INFINITY;
#pragma unroll
        for (int p = 0; p < P; p++) {
            int wi;
            if (p == 12) {
                wi = 12;
            } else {
                wi = p - root;
                if (wi < 0) wi += 12;
            }
            v[p] = tile[lr * P + p] * ws[wi];
            m = fmaxf(m, v[p]);
        }
        float s = 0.0f;
#pragma unroll
        for (int p = 0; p < P; p++) { v[p] = __expf(v[p] - m); s += v[p]; }
        const float r = __frcp_rn(s);
#pragma unroll
        for (int p = 0; p < P; p++) tile[lr * P + p] = v[p] * r;
    }
    __syncthreads();

    // ---- single bulk store: smem -> global (26624 B, one TMA op) ----
    if (tid == 0) {
        asm volatile("fence.proxy.async.shared::cta;" ::: "memory");
        asm volatile("cp.async.bulk.global.shared::cta.bulk_group [%0], [%1], %2;"
                     :: "l"(out + base), "r"(tile_a), "r"((uint32_t)TILE_BYTES)
                     : "memory");
        asm volatile("cp.async.bulk.commit_group;");
        // smem must stay live until TMA has read it; issuing thread holds CTA
        asm volatile("cp.async.bulk.wait_group.read 0;" ::: "memory");
    }
}

extern "C" void kernel_launch(void* const* d_in, const int* in_sizes, int n_in,
                              void* d_out, int out_size)
{
    const float* x = (const float*)d_in[0];   // chordal_pc_vector [65536,144,13]
    const float* w = (const float*)d_in[1];   // scale_degree_weight [13]
    float* out = (float*)d_out;

    const long long total = (long long)in_sizes[0];   // 122,683,392
    const int nblocks = (int)(total / TILE_FLOATS);   // 18432

    // Full smem carveout so 8 CTAs/SM fit (8 * ~26.8 KB).
    cudaFuncSetAttribute(chordal_softmax_kernel,
                         cudaFuncAttributePreferredSharedMemoryCarveout, 100);

    chordal_softmax_kernel<<<nblocks, RPB>>>(x, w, out);
}